// round 2
// baseline (speedup 1.0000x reference)
#include <cuda_runtime.h>
#include <cstdint>

#define NB  4
#define NTQ 512
#define NTK 512
#define NE  128
#define NF  256   // TWO_E

// Scratch (no allocations allowed)
__device__ float g_qproj[NB * NTQ * NE];               // 1 MB
__device__ float g_kproj[NB * NTK * NE];               // 1 MB
__device__ float g_p[(size_t)NB * NTK * NTQ];          // 4 MB (unnormalized exp)
__device__ float g_zr[NB * NTK];                       // 1/rowsum per (b,t)

__device__ __forceinline__ float tanh_fast(float x) {
    float y;
    asm("tanh.approx.f32 %0, %1;" : "=f"(y) : "f"(x));
    return y;
}

// ---------------------------------------------------------------------------
// Kernel A: projections.  C[r,e] = sum_f A[r,f] * W[f,e]
// A: [2048 x 256], W: [256 x 128].  blockIdx.y selects (query,W1) / (key,W2).
// Tile: 32 rows x 128 cols, BLK_K = 32, 256 threads, 4x4 micro-tile.
// ---------------------------------------------------------------------------
__global__ __launch_bounds__(256) void proj_kernel(
    const float* __restrict__ query, const float* __restrict__ key,
    const float* __restrict__ W1, const float* __restrict__ W2)
{
    const float* A; const float* W; float* C;
    if (blockIdx.y == 0) { A = query; W = W1; C = g_qproj; }
    else                 { A = key;   W = W2; C = g_kproj; }

    __shared__ float As[32][36];    // [k][m], padded
    __shared__ float Bs[32][128];   // [k][n]

    const int tid = threadIdx.x;
    const int tx = tid & 31;        // 32 threads over N (x4 cols)
    const int ty = tid >> 5;        // 8 threads over M  (x4 rows)
    const int row0 = blockIdx.x * 32;

    float acc[4][4];
    #pragma unroll
    for (int i = 0; i < 4; i++)
        #pragma unroll
        for (int j = 0; j < 4; j++) acc[i][j] = 0.f;

    for (int kk = 0; kk < NF; kk += 32) {
        {   // A chunk [32 rows x 32 k], transposed into As
            int r = tid >> 3;
            int c = (tid & 7) << 2;
            float4 v = *(const float4*)(A + (size_t)(row0 + r) * NF + kk + c);
            As[c + 0][r] = v.x; As[c + 1][r] = v.y;
            As[c + 2][r] = v.z; As[c + 3][r] = v.w;
        }
        #pragma unroll
        for (int i = 0; i < 4; i++) {   // W chunk [32 k x 128 n]
            int lin = tid + (i << 8);
            int k   = lin >> 5;
            int n4  = (lin & 31) << 2;
            *(float4*)&Bs[k][n4] = *(const float4*)(W + (size_t)(kk + k) * NE + n4);
        }
        __syncthreads();
        #pragma unroll
        for (int k = 0; k < 32; k++) {
            float4 av = *(const float4*)&As[k][ty << 2];
            float4 bv = *(const float4*)&Bs[k][tx << 2];
            float a[4] = {av.x, av.y, av.z, av.w};
            float b[4] = {bv.x, bv.y, bv.z, bv.w};
            #pragma unroll
            for (int i = 0; i < 4; i++)
                #pragma unroll
                for (int j = 0; j < 4; j++)
                    acc[i][j] += a[i] * b[j];
        }
        __syncthreads();
    }
    #pragma unroll
    for (int i = 0; i < 4; i++) {
        float4 v = make_float4(acc[i][0], acc[i][1], acc[i][2], acc[i][3]);
        *(float4*)(C + (size_t)(row0 + (ty << 2) + i) * NE + (tx << 2)) = v;
    }
}

// ---------------------------------------------------------------------------
// Kernel B: scores + exp + row-reciprocal.  MUFU(tanh)-bound.
// Block = (b, 8 t-rows); warp w owns t = t0+w; lane handles q = qc+lane, qc+lane+32.
// p[b,t,q] = exp(sum_e vc[e]*tanh(k[t,e]+q[q,e]))  (no max pass; |sjt| <= sum|vc| ~ 9)
// ---------------------------------------------------------------------------
__global__ __launch_bounds__(256) void score_kernel(const float* __restrict__ vc)
{
    __shared__ float ks[8][128];
    __shared__ float qs[64][129];   // +1 pad: lane-per-row reads are conflict-free
    __shared__ float vcs[128];

    const int b   = blockIdx.y;
    const int t0  = blockIdx.x << 3;
    const int tid = threadIdx.x;
    const int w    = tid >> 5;
    const int lane = tid & 31;

    {   // k tile [8 x 128]
        int lin = tid << 2;
        int r = lin >> 7, c = lin & 127;
        *(float4*)&ks[r][c] =
            *(const float4*)(g_kproj + (size_t)(b * NTK + t0 + r) * NE + c);
    }
    if (tid < 128) vcs[tid] = vc[tid];

    const int t = t0 + w;
    float* __restrict__ prow = g_p + ((size_t)b * NTK + t) * NTQ;
    float zsum = 0.f;

    for (int qc = 0; qc < NTQ; qc += 64) {
        __syncthreads();            // protect qs reuse
        #pragma unroll 8
        for (int i = 0; i < 32; i++) {   // q chunk [64 x 128], coalesced scalar loads
            int lin = tid + (i << 8);
            int r = lin >> 7, c = lin & 127;
            qs[r][c] = g_qproj[(size_t)(b * NTQ + qc + r) * NE + c];
        }
        __syncthreads();

        const float* __restrict__ kr = ks[w];        // warp broadcast
        const float* __restrict__ q0 = qs[lane];
        const float* __restrict__ q1 = qs[lane + 32];
        float acc0 = 0.f, acc1 = 0.f;
        #pragma unroll 16
        for (int e = 0; e < 128; e++) {
            float kv = kr[e];
            float vv = vcs[e];
            acc0 += vv * tanh_fast(kv + q0[e]);
            acc1 += vv * tanh_fast(kv + q1[e]);
        }
        float p0 = __expf(acc0);
        float p1 = __expf(acc1);
        prow[qc + lane]      = p0;
        prow[qc + lane + 32] = p1;
        zsum += p0 + p1;
    }

    #pragma unroll
    for (int off = 16; off; off >>= 1)
        zsum += __shfl_xor_sync(0xffffffffu, zsum, off);
    if (lane == 0) g_zr[b * NTK + t] = 1.0f / zsum;
}

// ---------------------------------------------------------------------------
// Kernel C: out[b,d,q] = sum_t (value[b,d,t] * zr[b,t]) * p[b,t,q]
// SGEMM M=256, N=512, K=512 per batch; tile 32x64, BLK_K=32, 2x4 micro-tile.
// 1/Z folded into the A (value) tile load.
// ---------------------------------------------------------------------------
__global__ __launch_bounds__(256) void out_kernel(
    const float* __restrict__ value, float* __restrict__ out)
{
    __shared__ float As[32][33];    // [k][m]
    __shared__ float Bs[32][64];    // [k][n]
    __shared__ float zrs[NTK];

    const int b   = blockIdx.z;
    const int n0  = blockIdx.x << 6;
    const int m0  = blockIdx.y << 5;
    const int tid = threadIdx.x;
    const int tx  = tid & 15;       // x4 cols
    const int ty  = tid >> 4;       // x2 rows

    zrs[tid]       = g_zr[b * NTK + tid];
    zrs[tid + 256] = g_zr[b * NTK + tid + 256];

    float acc[2][4];
    #pragma unroll
    for (int i = 0; i < 2; i++)
        #pragma unroll
        for (int j = 0; j < 4; j++) acc[i][j] = 0.f;

    const float* __restrict__ Av = value + (size_t)b * NF * NTK;   // [256][512]
    const float* __restrict__ Bp = g_p   + (size_t)b * NTK * NTQ;  // [512][512]

    for (int kk = 0; kk < NTK; kk += 32) {
        __syncthreads();   // also orders zrs write before first use
        {   // A chunk [32 m x 32 k] scaled by zr, transposed
            int m  = tid >> 3;
            int k4 = (tid & 7) << 2;
            float4 v = *(const float4*)(Av + (size_t)(m0 + m) * NTK + kk + k4);
            As[k4 + 0][m] = v.x * zrs[kk + k4 + 0];
            As[k4 + 1][m] = v.y * zrs[kk + k4 + 1];
            As[k4 + 2][m] = v.z * zrs[kk + k4 + 2];
            As[k4 + 3][m] = v.w * zrs[kk + k4 + 3];
        }
        #pragma unroll
        for (int i = 0; i < 2; i++) {   // B chunk [32 k x 64 n]
            int lin = tid + (i << 8);
            int k   = lin >> 4;
            int n4  = (lin & 15) << 2;
            *(float4*)&Bs[k][n4] = *(const float4*)(Bp + (size_t)(kk + k) * NTQ + n0 + n4);
        }
        __syncthreads();
        #pragma unroll
        for (int k = 0; k < 32; k++) {
            float a0 = As[k][ty * 2 + 0];
            float a1 = As[k][ty * 2 + 1];
            float4 bv = *(const float4*)&Bs[k][tx << 2];
            acc[0][0] += a0 * bv.x; acc[0][1] += a0 * bv.y;
            acc[0][2] += a0 * bv.z; acc[0][3] += a0 * bv.w;
            acc[1][0] += a1 * bv.x; acc[1][1] += a1 * bv.y;
            acc[1][2] += a1 * bv.z; acc[1][3] += a1 * bv.w;
        }
    }
    #pragma unroll
    for (int i = 0; i < 2; i++) {
        float4 v = make_float4(acc[i][0], acc[i][1], acc[i][2], acc[i][3]);
        *(float4*)(out + (size_t)(b * NF + m0 + ty * 2 + i) * NTQ + n0 + (tx << 2)) = v;
    }
}

// ---------------------------------------------------------------------------
extern "C" void kernel_launch(void* const* d_in, const int* in_sizes, int n_in,
                              void* d_out, int out_size)
{
    const float* query = (const float*)d_in[0];
    const float* key   = (const float*)d_in[1];
    const float* value = (const float*)d_in[2];
    const float* W1    = (const float*)d_in[3];
    const float* W2    = (const float*)d_in[4];
    const float* vc    = (const float*)d_in[5];
    float* out = (float*)d_out;

    proj_kernel <<<dim3(64, 2), 256>>>(query, key, W1, W2);   // 2048/32 rows x {q,k}
    score_kernel<<<dim3(64, 4), 256>>>(vc);                   // TK/8 x B
    out_kernel  <<<dim3(8, 8, 4), 256>>>(value, out);         // N/64 x M/32 x B
}

// round 3
// speedup vs baseline: 1.0579x; 1.0579x over previous
#include <cuda_runtime.h>
#include <cstdint>

#define NB  4
#define NTQ 512
#define NTK 512
#define NE  128
#define NF  256   // TWO_E

// Scratch (no allocations allowed)
__device__ float g_qproj[NB * NTQ * NE];               // 1 MB
__device__ float g_kproj[NB * NTK * NE];               // 1 MB
__device__ float g_p[(size_t)NB * NTK * NTQ];          // 4 MB (unnormalized exp)
__device__ float g_zr[NB * NTK];                       // 1/rowsum per (b,t)

__device__ __forceinline__ float tanh_fast(float x) {
    float y;
    asm("tanh.approx.f32 %0, %1;" : "=f"(y) : "f"(x));
    return y;
}

// ---------------------------------------------------------------------------
// Kernel A: projections.  C[r,e] = sum_f A[r,f] * W[f,e]
// A: [2048 x 256], W: [256 x 128].  blockIdx.y selects (query,W1) / (key,W2).
// Tile: 16 rows x 128 cols, BLK_K = 32, 128 threads, 4x4 micro-tile.
// grid = 128 x 2 = 256 blocks (no idle SMs, short blocks).
// ---------------------------------------------------------------------------
__global__ __launch_bounds__(128) void proj_kernel(
    const float* __restrict__ query, const float* __restrict__ key,
    const float* __restrict__ W1, const float* __restrict__ W2)
{
    const float* A; const float* W; float* C;
    if (blockIdx.y == 0) { A = query; W = W1; C = g_qproj; }
    else                 { A = key;   W = W2; C = g_kproj; }

    __shared__ float As[32][20];    // [k][m], 16 rows + pad (row = 80B, 16B aligned)
    __shared__ float Bs[32][128];   // [k][n]

    const int tid = threadIdx.x;
    const int tx = tid & 31;        // 32 threads over N (x4 cols)
    const int ty = tid >> 5;        // 4 threads over M  (x4 rows)
    const int row0 = blockIdx.x * 16;

    float acc[4][4];
    #pragma unroll
    for (int i = 0; i < 4; i++)
        #pragma unroll
        for (int j = 0; j < 4; j++) acc[i][j] = 0.f;

    for (int kk = 0; kk < NF; kk += 32) {
        {   // A chunk [16 rows x 32 k], transposed into As: 1 float4 / thread
            int r = tid >> 3;
            int c = (tid & 7) << 2;
            float4 v = *(const float4*)(A + (size_t)(row0 + r) * NF + kk + c);
            As[c + 0][r] = v.x; As[c + 1][r] = v.y;
            As[c + 2][r] = v.z; As[c + 3][r] = v.w;
        }
        #pragma unroll
        for (int i = 0; i < 8; i++) {   // W chunk [32 k x 128 n]: 8 float4 / thread
            int lin = tid + (i << 7);
            int k   = lin >> 5;
            int n4  = (lin & 31) << 2;
            *(float4*)&Bs[k][n4] = *(const float4*)(W + (size_t)(kk + k) * NE + n4);
        }
        __syncthreads();
        #pragma unroll
        for (int k = 0; k < 32; k++) {
            float4 av = *(const float4*)&As[k][ty << 2];
            float4 bv = *(const float4*)&Bs[k][tx << 2];
            float a[4] = {av.x, av.y, av.z, av.w};
            float b[4] = {bv.x, bv.y, bv.z, bv.w};
            #pragma unroll
            for (int i = 0; i < 4; i++)
                #pragma unroll
                for (int j = 0; j < 4; j++)
                    acc[i][j] += a[i] * b[j];
        }
        __syncthreads();
    }
    #pragma unroll
    for (int i = 0; i < 4; i++) {
        float4 v = make_float4(acc[i][0], acc[i][1], acc[i][2], acc[i][3]);
        *(float4*)(C + (size_t)(row0 + (ty << 2) + i) * NE + (tx << 2)) = v;
    }
}

// ---------------------------------------------------------------------------
// Kernel B: scores + exp + row-reciprocal.  MUFU(tanh)-bound.
// Block = (b, 8 t-rows); warp w owns t = t0+w; lane handles q = qc+lane, qc+lane+32.
// p[b,t,q] = exp(sum_e vc[e]*tanh(k[t,e]+q[q,e]))  (no max pass; |sjt| <= sum|vc| ~ 9)
// ---------------------------------------------------------------------------
__global__ __launch_bounds__(256) void score_kernel(const float* __restrict__ vc)
{
    __shared__ float ks[8][128];
    __shared__ float qs[64][129];   // +1 pad: lane-per-row reads are conflict-free
    __shared__ float vcs[128];

    const int b   = blockIdx.y;
    const int t0  = blockIdx.x << 3;
    const int tid = threadIdx.x;
    const int w    = tid >> 5;
    const int lane = tid & 31;

    {   // k tile [8 x 128]
        int lin = tid << 2;
        int r = lin >> 7, c = lin & 127;
        *(float4*)&ks[r][c] =
            *(const float4*)(g_kproj + (size_t)(b * NTK + t0 + r) * NE + c);
    }
    if (tid < 128) vcs[tid] = vc[tid];

    const int t = t0 + w;
    float* __restrict__ prow = g_p + ((size_t)b * NTK + t) * NTQ;
    float zsum = 0.f;

    for (int qc = 0; qc < NTQ; qc += 64) {
        __syncthreads();            // protect qs reuse
        #pragma unroll 8
        for (int i = 0; i < 32; i++) {   // q chunk [64 x 128], coalesced scalar loads
            int lin = tid + (i << 8);
            int r = lin >> 7, c = lin & 127;
            qs[r][c] = g_qproj[(size_t)(b * NTQ + qc + r) * NE + c];
        }
        __syncthreads();

        const float* __restrict__ kr = ks[w];        // warp broadcast
        const float* __restrict__ q0 = qs[lane];
        const float* __restrict__ q1 = qs[lane + 32];
        float acc0 = 0.f, acc1 = 0.f;
        #pragma unroll 16
        for (int e = 0; e < 128; e++) {
            float kv = kr[e];
            float vv = vcs[e];
            acc0 += vv * tanh_fast(kv + q0[e]);
            acc1 += vv * tanh_fast(kv + q1[e]);
        }
        float p0 = __expf(acc0);
        float p1 = __expf(acc1);
        prow[qc + lane]      = p0;
        prow[qc + lane + 32] = p1;
        zsum += p0 + p1;
    }

    #pragma unroll
    for (int off = 16; off; off >>= 1)
        zsum += __shfl_xor_sync(0xffffffffu, zsum, off);
    if (lane == 0) g_zr[b * NTK + t] = 1.0f / zsum;
}

// ---------------------------------------------------------------------------
// Kernel C: out[b,d,q] = sum_t (value[b,d,t] * zr[b,t]) * p[b,t,q]
// SGEMM M=256, N=512, K=512 per batch; tile 32x64, 128 threads, 4x4 micro-tile.
// grid = 8 x 8 x 4 = 256 blocks.  1/Z folded into the A (value) tile load.
// ---------------------------------------------------------------------------
__global__ __launch_bounds__(128) void out_kernel(
    const float* __restrict__ value, float* __restrict__ out)
{
    __shared__ float As[32][36];    // [k][m], 32 rows + pad (row = 144B, 16B aligned)
    __shared__ float Bs[32][64];    // [k][n]
    __shared__ float zrs[NTK];

    const int b   = blockIdx.z;
    const int n0  = blockIdx.x << 6;
    const int m0  = blockIdx.y << 5;
    const int tid = threadIdx.x;
    const int tx  = tid & 15;       // 16 over N (x4 cols)
    const int ty  = tid >> 4;       // 8 over M  (x4 rows)

    #pragma unroll
    for (int i = 0; i < 4; i++)
        zrs[tid + (i << 7)] = g_zr[b * NTK + tid + (i << 7)];

    float acc[4][4];
    #pragma unroll
    for (int i = 0; i < 4; i++)
        #pragma unroll
        for (int j = 0; j < 4; j++) acc[i][j] = 0.f;

    const float* __restrict__ Av = value + (size_t)b * NF * NTK;   // [256][512]
    const float* __restrict__ Bp = g_p   + (size_t)b * NTK * NTQ;  // [512][512]

    for (int kk = 0; kk < NTK; kk += 32) {
        __syncthreads();   // also orders zrs writes before first use
        {   // A chunk [32 m x 32 k] scaled by zr, transposed: 2 float4 / thread
            int m  = tid >> 2;
            int k8 = (tid & 3) << 3;
            const float* src = Av + (size_t)(m0 + m) * NTK + kk + k8;
            float4 v0 = *(const float4*)(src);
            float4 v1 = *(const float4*)(src + 4);
            As[k8 + 0][m] = v0.x * zrs[kk + k8 + 0];
            As[k8 + 1][m] = v0.y * zrs[kk + k8 + 1];
            As[k8 + 2][m] = v0.z * zrs[kk + k8 + 2];
            As[k8 + 3][m] = v0.w * zrs[kk + k8 + 3];
            As[k8 + 4][m] = v1.x * zrs[kk + k8 + 4];
            As[k8 + 5][m] = v1.y * zrs[kk + k8 + 5];
            As[k8 + 6][m] = v1.z * zrs[kk + k8 + 6];
            As[k8 + 7][m] = v1.w * zrs[kk + k8 + 7];
        }
        #pragma unroll
        for (int i = 0; i < 4; i++) {   // B chunk [32 k x 64 n]: 4 float4 / thread
            int lin = tid + (i << 7);
            int k   = lin >> 4;
            int n4  = (lin & 15) << 2;
            *(float4*)&Bs[k][n4] = *(const float4*)(Bp + (size_t)(kk + k) * NTQ + n0 + n4);
        }
        __syncthreads();
        #pragma unroll
        for (int k = 0; k < 32; k++) {
            float4 av = *(const float4*)&As[k][ty << 2];
            float4 bv = *(const float4*)&Bs[k][tx << 2];
            float a[4] = {av.x, av.y, av.z, av.w};
            float bb[4] = {bv.x, bv.y, bv.z, bv.w};
            #pragma unroll
            for (int i = 0; i < 4; i++)
                #pragma unroll
                for (int j = 0; j < 4; j++)
                    acc[i][j] += a[i] * bb[j];
        }
    }
    #pragma unroll
    for (int i = 0; i < 4; i++) {
        float4 v = make_float4(acc[i][0], acc[i][1], acc[i][2], acc[i][3]);
        *(float4*)(out + (size_t)(b * NF + m0 + (ty << 2) + i) * NTQ + n0 + (tx << 2)) = v;
    }
}

// ---------------------------------------------------------------------------
extern "C" void kernel_launch(void* const* d_in, const int* in_sizes, int n_in,
                              void* d_out, int out_size)
{
    const float* query = (const float*)d_in[0];
    const float* key   = (const float*)d_in[1];
    const float* value = (const float*)d_in[2];
    const float* W1    = (const float*)d_in[3];
    const float* W2    = (const float*)d_in[4];
    const float* vc    = (const float*)d_in[5];
    float* out = (float*)d_out;

    proj_kernel <<<dim3(128, 2), 128>>>(query, key, W1, W2);  // 2048/16 rows x {q,k}
    score_kernel<<<dim3(64, 4), 256>>>(vc);                   // TK/8 x B
    out_kernel  <<<dim3(8, 8, 4), 128>>>(value, out);         // N/64 x M/32 x B
}

// round 4
// speedup vs baseline: 1.1429x; 1.0804x over previous
#include <cuda_runtime.h>
#include <cstdint>

#define NB  4
#define NTQ 512
#define NTK 512
#define NE  128
#define NF  256   // TWO_E

// Scratch (no allocations allowed)
__device__ float g_qproj[NB * NTQ * NE];               // 1 MB
__device__ float g_kproj[NB * NTK * NE];               // 1 MB
__device__ float g_p[(size_t)NB * NTK * NTQ];          // 4 MB (unnormalized exp)
__device__ float g_zr[NB * NTK];                       // 1/rowsum per (b,t)

__device__ __forceinline__ float tanh_fast(float x) {
    float y;
    asm("tanh.approx.f32 %0, %1;" : "=f"(y) : "f"(x));
    return y;
}

// ---------------------------------------------------------------------------
// Kernel A: projections.  C[r,e] = sum_f A[r,f] * W[f,e]
// A: [2048 x 256], W: [256 x 128].  blockIdx.y selects (query,W1) / (key,W2).
// Tile 16x128, BLK_K=32, 128 threads, 4x4 micro-tile.
// Software-pipelined: ping-pong smem + register prefetch, ONE sync per iter.
// ---------------------------------------------------------------------------
__global__ __launch_bounds__(128) void proj_kernel(
    const float* __restrict__ query, const float* __restrict__ key,
    const float* __restrict__ W1, const float* __restrict__ W2)
{
    const float* A; const float* W; float* C;
    if (blockIdx.y == 0) { A = query; W = W1; C = g_qproj; }
    else                 { A = key;   W = W2; C = g_kproj; }

    __shared__ float As[2][32][20];    // [buf][k][m], 16 rows + pad
    __shared__ float Bs[2][32][128];   // [buf][k][n]

    const int tid = threadIdx.x;
    const int tx = tid & 31;           // 32 threads over N (x4 cols)
    const int ty = tid >> 5;           // 4 threads over M  (x4 rows)
    const int row0 = blockIdx.x * 16;

    // load addressing
    const int ar = tid >> 3;           // A row 0..15
    const int ac = (tid & 7) << 2;     // A k-col base
    const int wk = tid >> 5;           // W k base (stride 4)
    const int wn = (tid & 31) << 2;    // W n base
    const float* Aptr = A + (size_t)(row0 + ar) * NF + ac;
    const float* Wptr = W + (size_t)wk * NE + wn;

    float4 areg;
    float4 wreg[8];

    // prefetch tile 0
    areg = *(const float4*)(Aptr);
    #pragma unroll
    for (int i = 0; i < 8; i++)
        wreg[i] = *(const float4*)(Wptr + (size_t)(4 * i) * NE);

    // store tile 0 -> buf 0
    As[0][ac + 0][ar] = areg.x; As[0][ac + 1][ar] = areg.y;
    As[0][ac + 2][ar] = areg.z; As[0][ac + 3][ar] = areg.w;
    #pragma unroll
    for (int i = 0; i < 8; i++)
        *(float4*)&Bs[0][wk + 4 * i][wn] = wreg[i];
    __syncthreads();

    float acc[4][4];
    #pragma unroll
    for (int i = 0; i < 4; i++)
        #pragma unroll
        for (int j = 0; j < 4; j++) acc[i][j] = 0.f;

    #pragma unroll
    for (int it = 0; it < 8; it++) {
        const int buf = it & 1;
        if (it < 7) {   // prefetch next tile into regs (overlaps compute)
            areg = *(const float4*)(Aptr + (it + 1) * 32);
            #pragma unroll
            for (int i = 0; i < 8; i++)
                wreg[i] = *(const float4*)(Wptr + (size_t)((it + 1) * 32 + 4 * i) * NE);
        }
        #pragma unroll
        for (int k = 0; k < 32; k++) {
            float4 av = *(const float4*)&As[buf][k][ty << 2];
            float4 bv = *(const float4*)&Bs[buf][k][tx << 2];
            float a[4] = {av.x, av.y, av.z, av.w};
            float b[4] = {bv.x, bv.y, bv.z, bv.w};
            #pragma unroll
            for (int i = 0; i < 4; i++)
                #pragma unroll
                for (int j = 0; j < 4; j++)
                    acc[i][j] += a[i] * b[j];
        }
        if (it < 7) {   // store into the other buffer; safe pre-sync (see theory)
            const int nb = buf ^ 1;
            As[nb][ac + 0][ar] = areg.x; As[nb][ac + 1][ar] = areg.y;
            As[nb][ac + 2][ar] = areg.z; As[nb][ac + 3][ar] = areg.w;
            #pragma unroll
            for (int i = 0; i < 8; i++)
                *(float4*)&Bs[nb][wk + 4 * i][wn] = wreg[i];
            __syncthreads();
        }
    }

    #pragma unroll
    for (int i = 0; i < 4; i++) {
        float4 v = make_float4(acc[i][0], acc[i][1], acc[i][2], acc[i][3]);
        *(float4*)(C + (size_t)(row0 + (ty << 2) + i) * NE + (tx << 2)) = v;
    }
}

// ---------------------------------------------------------------------------
// Kernel B: scores + exp + row-reciprocal.  MUFU(tanh)-bound.
// Block = (b, 8 t-rows), 256 threads; warp w owns t=t0+w; lane owns q=ch*32+lane.
// q tiles of 32 rows, double-buffered in smem with register prefetch.
// p[b,t,q] = exp(sum_e vc[e]*tanh(k[t,e]+q[q,e]))  (no max pass; |sjt| <= ~9)
// ---------------------------------------------------------------------------
__global__ __launch_bounds__(256) void score_kernel(const float* __restrict__ vc)
{
    __shared__ float ks[8][128];
    __shared__ float qs[2][32][129];   // +1 pad: lane-per-row reads conflict-free
    __shared__ float vcs[128];

    const int b   = blockIdx.y;
    const int t0  = blockIdx.x << 3;
    const int tid = threadIdx.x;
    const int w    = tid >> 5;
    const int lane = tid & 31;

    {   // k tile [8 x 128]
        int lin = tid << 2;
        int r = lin >> 7, c = lin & 127;
        *(float4*)&ks[r][c] =
            *(const float4*)(g_kproj + (size_t)(b * NTK + t0 + r) * NE + c);
    }
    if (tid < 128) vcs[tid] = vc[tid];

    // q chunk load mapping: thread covers column c0, rows rbase, rbase+2, ...
    const int c0    = tid & 127;
    const int rbase = tid >> 7;        // 0 or 1
    const float* qbase = g_qproj + (size_t)b * NTQ * NE + rbase * NE + c0;

    float pref[16];
    #pragma unroll
    for (int i = 0; i < 16; i++)       // chunk 0
        pref[i] = qbase[(size_t)(2 * i) * NE];
    #pragma unroll
    for (int i = 0; i < 16; i++)
        qs[0][rbase + 2 * i][c0] = pref[i];
    __syncthreads();

    const int t = t0 + w;
    float* __restrict__ prow = g_p + ((size_t)b * NTK + t) * NTQ;
    float zsum = 0.f;

    for (int ch = 0; ch < 16; ch++) {
        const int buf = ch & 1;
        if (ch < 15) {                 // prefetch next 32-q chunk (overlaps tanh loop)
            const float* src = qbase + (size_t)(ch + 1) * 32 * NE;
            #pragma unroll
            for (int i = 0; i < 16; i++)
                pref[i] = src[(size_t)(2 * i) * NE];
        }

        const float* __restrict__ kr = ks[w];          // warp broadcast
        const float* __restrict__ q0 = qs[buf][lane];
        float acc0 = 0.f;
        #pragma unroll 16
        for (int e = 0; e < 128; e++)
            acc0 += vcs[e] * tanh_fast(kr[e] + q0[e]);

        float p0 = __expf(acc0);
        prow[ch * 32 + lane] = p0;
        zsum += p0;

        if (ch < 15) {
            __syncthreads();           // all warps done with buf^1 (chunk ch-1)
            #pragma unroll
            for (int i = 0; i < 16; i++)
                qs[buf ^ 1][rbase + 2 * i][c0] = pref[i];
            __syncthreads();
        }
    }

    #pragma unroll
    for (int off = 16; off; off >>= 1)
        zsum += __shfl_xor_sync(0xffffffffu, zsum, off);
    if (lane == 0) g_zr[b * NTK + t] = 1.0f / zsum;
}

// ---------------------------------------------------------------------------
// Kernel C: out[b,d,q] = sum_t (value[b,d,t] * zr[b,t]) * p[b,t,q]
// SGEMM M=256, N=512, K=512 per batch; tile 32x64, 128 threads, 4x4 micro-tile.
// Software-pipelined ping-pong smem, ONE sync per K-iter. 1/Z folded into A load.
// ---------------------------------------------------------------------------
__global__ __launch_bounds__(128) void out_kernel(
    const float* __restrict__ value, float* __restrict__ out)
{
    __shared__ float As[2][32][36];    // [buf][k][m]
    __shared__ float Bs[2][32][64];    // [buf][k][n]
    __shared__ float zrs[NTK];

    const int b   = blockIdx.z;
    const int n0  = blockIdx.x << 6;
    const int m0  = blockIdx.y << 5;
    const int tid = threadIdx.x;
    const int tx  = tid & 15;          // 16 over N (x4 cols)
    const int ty  = tid >> 4;          // 8 over M  (x4 rows)

    #pragma unroll
    for (int i = 0; i < 4; i++)
        zrs[tid + (i << 7)] = g_zr[b * NTK + tid + (i << 7)];

    // load addressing
    const int am = tid >> 2;           // A m-row 0..31
    const int ak = (tid & 3) << 3;     // A k base (8 wide)
    const int bk = tid >> 4;           // B k base (stride 8)
    const int bn = (tid & 15) << 2;    // B n base
    const float* Av = value + (size_t)b * NF * NTK + (size_t)(m0 + am) * NTK + ak;
    const float* Bp = g_p   + (size_t)b * NTK * NTQ + (size_t)bk * NTQ + n0 + bn;

    float4 a0, a1;
    float4 breg[4];

    // prefetch tile 0
    a0 = *(const float4*)(Av);
    a1 = *(const float4*)(Av + 4);
    #pragma unroll
    for (int i = 0; i < 4; i++)
        breg[i] = *(const float4*)(Bp + (size_t)(8 * i) * NTQ);

    __syncthreads();                   // zrs visible to all

    {   // store tile 0 -> buf 0 (A scaled by zr)
        As[0][ak + 0][am] = a0.x * zrs[ak + 0];
        As[0][ak + 1][am] = a0.y * zrs[ak + 1];
        As[0][ak + 2][am] = a0.z * zrs[ak + 2];
        As[0][ak + 3][am] = a0.w * zrs[ak + 3];
        As[0][ak + 4][am] = a1.x * zrs[ak + 4];
        As[0][ak + 5][am] = a1.y * zrs[ak + 5];
        As[0][ak + 6][am] = a1.z * zrs[ak + 6];
        As[0][ak + 7][am] = a1.w * zrs[ak + 7];
        #pragma unroll
        for (int i = 0; i < 4; i++)
            *(float4*)&Bs[0][bk + 8 * i][bn] = breg[i];
    }
    __syncthreads();

    float acc[4][4];
    #pragma unroll
    for (int i = 0; i < 4; i++)
        #pragma unroll
        for (int j = 0; j < 4; j++) acc[i][j] = 0.f;

    for (int it = 0; it < 16; it++) {
        const int buf = it & 1;
        const int kk  = (it + 1) << 5;
        if (it < 15) {                 // prefetch next tile
            a0 = *(const float4*)(Av + kk);
            a1 = *(const float4*)(Av + kk + 4);
            #pragma unroll
            for (int i = 0; i < 4; i++)
                breg[i] = *(const float4*)(Bp + (size_t)(kk + 8 * i) * NTQ);
        }
        #pragma unroll
        for (int k = 0; k < 32; k++) {
            float4 av = *(const float4*)&As[buf][k][ty << 2];
            float4 bv = *(const float4*)&Bs[buf][k][tx << 2];
            float a[4] = {av.x, av.y, av.z, av.w};
            float bb[4] = {bv.x, bv.y, bv.z, bv.w};
            #pragma unroll
            for (int i = 0; i < 4; i++)
                #pragma unroll
                for (int j = 0; j < 4; j++)
                    acc[i][j] += a[i] * bb[j];
        }
        if (it < 15) {                 // store into other buffer; safe pre-sync
            const int nb = buf ^ 1;
            As[nb][ak + 0][am] = a0.x * zrs[kk + ak + 0];
            As[nb][ak + 1][am] = a0.y * zrs[kk + ak + 1];
            As[nb][ak + 2][am] = a0.z * zrs[kk + ak + 2];
            As[nb][ak + 3][am] = a0.w * zrs[kk + ak + 3];
            As[nb][ak + 4][am] = a1.x * zrs[kk + ak + 4];
            As[nb][ak + 5][am] = a1.y * zrs[kk + ak + 5];
            As[nb][ak + 6][am] = a1.z * zrs[kk + ak + 6];
            As[nb][ak + 7][am] = a1.w * zrs[kk + ak + 7];
            #pragma unroll
            for (int i = 0; i < 4; i++)
                *(float4*)&Bs[nb][bk + 8 * i][bn] = breg[i];
            __syncthreads();
        }
    }

    #pragma unroll
    for (int i = 0; i < 4; i++) {
        float4 v = make_float4(acc[i][0], acc[i][1], acc[i][2], acc[i][3]);
        *(float4*)(out + (size_t)(b * NF + m0 + (ty << 2) + i) * NTQ + n0 + (tx << 2)) = v;
    }
}

// ---------------------------------------------------------------------------
extern "C" void kernel_launch(void* const* d_in, const int* in_sizes, int n_in,
                              void* d_out, int out_size)
{
    const float* query = (const float*)d_in[0];
    const float* key   = (const float*)d_in[1];
    const float* value = (const float*)d_in[2];
    const float* W1    = (const float*)d_in[3];
    const float* W2    = (const float*)d_in[4];
    const float* vc    = (const float*)d_in[5];
    float* out = (float*)d_out;

    proj_kernel <<<dim3(128, 2), 128>>>(query, key, W1, W2);  // 2048/16 rows x {q,k}
    score_kernel<<<dim3(64, 4), 256>>>(vc);                   // TK/8 x B
    out_kernel  <<<dim3(8, 8, 4), 128>>>(value, out);         // N/64 x M/32 x B
}

// round 5
// speedup vs baseline: 1.1460x; 1.0027x over previous
#include <cuda_runtime.h>
#include <cstdint>

#define NB  4
#define NTQ 512
#define NTK 512
#define NE  128
#define NF  256   // TWO_E

// Scratch (no allocations allowed)
__device__ float g_qproj[NB * NTQ * NE];               // 1 MB
__device__ float g_kproj[NB * NTK * NE];               // 1 MB
__device__ float g_p[(size_t)NB * NTK * NTQ];          // 4 MB (unnormalized exp)
__device__ float g_zr[NB * NTK];                       // 1/rowsum per (b,t)

__device__ __forceinline__ float tanh_fast(float x) {
    float y;
    asm("tanh.approx.f32 %0, %1;" : "=f"(y) : "f"(x));
    return y;
}

// ---- packed fp32x2 helpers (Blackwell FFMA2; bit-exact IEEE fp32 FMA) ----
__device__ __forceinline__ unsigned long long pack2(float x, float y) {
    unsigned long long r;
    asm("mov.b64 %0, {%1, %2};" : "=l"(r) : "f"(x), "f"(y));
    return r;
}
__device__ __forceinline__ void ffma2(unsigned long long& d,
                                      unsigned long long a, unsigned long long b) {
    asm("fma.rn.f32x2 %0, %1, %2, %0;" : "+l"(d) : "l"(a), "l"(b));
}
__device__ __forceinline__ float2 unpack2(unsigned long long v) {
    float2 f;
    asm("mov.b64 {%0, %1}, %2;" : "=f"(f.x), "=f"(f.y) : "l"(v));
    return f;
}

// ---------------------------------------------------------------------------
// Kernel A: projections.  C[r,e] = sum_f A[r,f] * W[f,e]
// A: [2048 x 256], W: [256 x 128].  blockIdx.y selects (query,W1) / (key,W2).
// Tile 16x128, BLK_K=32, 128 threads, 4x4 micro-tile, f32x2 inner product.
// Software-pipelined: ping-pong smem + register prefetch, ONE sync per iter.
// ---------------------------------------------------------------------------
__global__ __launch_bounds__(128) void proj_kernel(
    const float* __restrict__ query, const float* __restrict__ key,
    const float* __restrict__ W1, const float* __restrict__ W2)
{
    const float* A; const float* W; float* C;
    if (blockIdx.y == 0) { A = query; W = W1; C = g_qproj; }
    else                 { A = key;   W = W2; C = g_kproj; }

    __shared__ float As[2][32][20];    // [buf][k][m], 16 rows + pad (80B row, 16B-mult)
    __shared__ float Bs[2][32][128];   // [buf][k][n]

    const int tid = threadIdx.x;
    const int tx = tid & 31;           // 32 threads over N (x4 cols)
    const int ty = tid >> 5;           // 4 threads over M  (x4 rows)
    const int row0 = blockIdx.x * 16;

    // load addressing
    const int ar = tid >> 3;           // A row 0..15
    const int ac = (tid & 7) << 2;     // A k-col base
    const int wk = tid >> 5;           // W k base (stride 4)
    const int wn = (tid & 31) << 2;    // W n base
    const float* Aptr = A + (size_t)(row0 + ar) * NF + ac;
    const float* Wptr = W + (size_t)wk * NE + wn;

    float4 areg;
    float4 wreg[8];

    // prefetch tile 0
    areg = *(const float4*)(Aptr);
    #pragma unroll
    for (int i = 0; i < 8; i++)
        wreg[i] = *(const float4*)(Wptr + (size_t)(4 * i) * NE);

    // store tile 0 -> buf 0
    As[0][ac + 0][ar] = areg.x; As[0][ac + 1][ar] = areg.y;
    As[0][ac + 2][ar] = areg.z; As[0][ac + 3][ar] = areg.w;
    #pragma unroll
    for (int i = 0; i < 8; i++)
        *(float4*)&Bs[0][wk + 4 * i][wn] = wreg[i];
    __syncthreads();

    unsigned long long acc2[4][2];     // [m-row][n-pair]: 4x4 fp32 accumulators
    #pragma unroll
    for (int i = 0; i < 4; i++) { acc2[i][0] = 0ULL; acc2[i][1] = 0ULL; }

    #pragma unroll
    for (int it = 0; it < 8; it++) {
        const int buf = it & 1;
        if (it < 7) {   // prefetch next tile into regs (overlaps compute)
            areg = *(const float4*)(Aptr + (it + 1) * 32);
            #pragma unroll
            for (int i = 0; i < 8; i++)
                wreg[i] = *(const float4*)(Wptr + (size_t)((it + 1) * 32 + 4 * i) * NE);
        }
        #pragma unroll
        for (int k = 0; k < 32; k++) {
            float4 av = *(const float4*)&As[buf][k][ty << 2];
            ulonglong2 bp = *(const ulonglong2*)&Bs[buf][k][tx << 2];
            float a[4] = {av.x, av.y, av.z, av.w};
            #pragma unroll
            for (int i = 0; i < 4; i++) {
                unsigned long long aa = pack2(a[i], a[i]);
                ffma2(acc2[i][0], aa, bp.x);
                ffma2(acc2[i][1], aa, bp.y);
            }
        }
        if (it < 7) {   // store into the other buffer; safe pre-sync
            const int nb = buf ^ 1;
            As[nb][ac + 0][ar] = areg.x; As[nb][ac + 1][ar] = areg.y;
            As[nb][ac + 2][ar] = areg.z; As[nb][ac + 3][ar] = areg.w;
            #pragma unroll
            for (int i = 0; i < 8; i++)
                *(float4*)&Bs[nb][wk + 4 * i][wn] = wreg[i];
            __syncthreads();
        }
    }

    #pragma unroll
    for (int i = 0; i < 4; i++) {
        float2 f01 = unpack2(acc2[i][0]);
        float2 f23 = unpack2(acc2[i][1]);
        float4 v = make_float4(f01.x, f01.y, f23.x, f23.y);
        *(float4*)(C + (size_t)(row0 + (ty << 2) + i) * NE + (tx << 2)) = v;
    }
}

// ---------------------------------------------------------------------------
// Kernel B: scores + exp + row-reciprocal.  MUFU(tanh)-bound (at floor).
// Block = (b, 8 t-rows), 256 threads; warp w owns t=t0+w; lane owns q=ch*32+lane.
// q tiles of 32 rows, double-buffered in smem with register prefetch.
// p[b,t,q] = exp(sum_e vc[e]*tanh(k[t,e]+q[q,e]))  (no max pass; |sjt| <= ~9)
// ---------------------------------------------------------------------------
__global__ __launch_bounds__(256) void score_kernel(const float* __restrict__ vc)
{
    __shared__ float ks[8][128];
    __shared__ float qs[2][32][129];   // +1 pad: lane-per-row reads conflict-free
    __shared__ float vcs[128];

    const int b   = blockIdx.y;
    const int t0  = blockIdx.x << 3;
    const int tid = threadIdx.x;
    const int w    = tid >> 5;
    const int lane = tid & 31;

    {   // k tile [8 x 128]
        int lin = tid << 2;
        int r = lin >> 7, c = lin & 127;
        *(float4*)&ks[r][c] =
            *(const float4*)(g_kproj + (size_t)(b * NTK + t0 + r) * NE + c);
    }
    if (tid < 128) vcs[tid] = vc[tid];

    // q chunk load mapping: thread covers column c0, rows rbase, rbase+2, ...
    const int c0    = tid & 127;
    const int rbase = tid >> 7;        // 0 or 1
    const float* qbase = g_qproj + (size_t)b * NTQ * NE + rbase * NE + c0;

    float pref[16];
    #pragma unroll
    for (int i = 0; i < 16; i++)       // chunk 0
        pref[i] = qbase[(size_t)(2 * i) * NE];
    #pragma unroll
    for (int i = 0; i < 16; i++)
        qs[0][rbase + 2 * i][c0] = pref[i];
    __syncthreads();

    const int t = t0 + w;
    float* __restrict__ prow = g_p + ((size_t)b * NTK + t) * NTQ;
    float zsum = 0.f;

    for (int ch = 0; ch < 16; ch++) {
        const int buf = ch & 1;
        if (ch < 15) {                 // prefetch next 32-q chunk (overlaps tanh loop)
            const float* src = qbase + (size_t)(ch + 1) * 32 * NE;
            #pragma unroll
            for (int i = 0; i < 16; i++)
                pref[i] = src[(size_t)(2 * i) * NE];
        }

        const float* __restrict__ kr = ks[w];          // warp broadcast
        const float* __restrict__ q0 = qs[buf][lane];
        float acc0 = 0.f;
        #pragma unroll 16
        for (int e = 0; e < 128; e++)
            acc0 += vcs[e] * tanh_fast(kr[e] + q0[e]);

        float p0 = __expf(acc0);
        prow[ch * 32 + lane] = p0;
        zsum += p0;

        if (ch < 15) {
            __syncthreads();           // all warps done with buf^1 (chunk ch-1)
            #pragma unroll
            for (int i = 0; i < 16; i++)
                qs[buf ^ 1][rbase + 2 * i][c0] = pref[i];
            __syncthreads();
        }
    }

    #pragma unroll
    for (int off = 16; off; off >>= 1)
        zsum += __shfl_xor_sync(0xffffffffu, zsum, off);
    if (lane == 0) g_zr[b * NTK + t] = 1.0f / zsum;
}

// ---------------------------------------------------------------------------
// Kernel C: out[b,d,q] = sum_t (value[b,d,t] * zr[b,t]) * p[b,t,q]
// SGEMM M=256, N=512, K=512 per batch; tile 32x64, 128 threads, 4x4 micro-tile,
// f32x2 inner product. Pipelined ping-pong smem, ONE sync per K-iter.
// 1/Z folded into the A (value) tile load.
// ---------------------------------------------------------------------------
__global__ __launch_bounds__(128) void out_kernel(
    const float* __restrict__ value, float* __restrict__ out)
{
    __shared__ float As[2][32][36];    // [buf][k][m] (144B row, 16B-mult)
    __shared__ float Bs[2][32][64];    // [buf][k][n]
    __shared__ float zrs[NTK];

    const int b   = blockIdx.z;
    const int n0  = blockIdx.x << 6;
    const int m0  = blockIdx.y << 5;
    const int tid = threadIdx.x;
    const int tx  = tid & 15;          // 16 over N (x4 cols)
    const int ty  = tid >> 4;          // 8 over M  (x4 rows)

    #pragma unroll
    for (int i = 0; i < 4; i++)
        zrs[tid + (i << 7)] = g_zr[b * NTK + tid + (i << 7)];

    // load addressing
    const int am = tid >> 2;           // A m-row 0..31
    const int ak = (tid & 3) << 3;     // A k base (8 wide)
    const int bk = tid >> 4;           // B k base (stride 8)
    const int bn = (tid & 15) << 2;    // B n base
    const float* Av = value + (size_t)b * NF * NTK + (size_t)(m0 + am) * NTK + ak;
    const float* Bp = g_p   + (size_t)b * NTK * NTQ + (size_t)bk * NTQ + n0 + bn;

    float4 a0, a1;
    float4 breg[4];

    // prefetch tile 0
    a0 = *(const float4*)(Av);
    a1 = *(const float4*)(Av + 4);
    #pragma unroll
    for (int i = 0; i < 4; i++)
        breg[i] = *(const float4*)(Bp + (size_t)(8 * i) * NTQ);

    __syncthreads();                   // zrs visible to all

    {   // store tile 0 -> buf 0 (A scaled by zr)
        As[0][ak + 0][am] = a0.x * zrs[ak + 0];
        As[0][ak + 1][am] = a0.y * zrs[ak + 1];
        As[0][ak + 2][am] = a0.z * zrs[ak + 2];
        As[0][ak + 3][am] = a0.w * zrs[ak + 3];
        As[0][ak + 4][am] = a1.x * zrs[ak + 4];
        As[0][ak + 5][am] = a1.y * zrs[ak + 5];
        As[0][ak + 6][am] = a1.z * zrs[ak + 6];
        As[0][ak + 7][am] = a1.w * zrs[ak + 7];
        #pragma unroll
        for (int i = 0; i < 4; i++)
            *(float4*)&Bs[0][bk + 8 * i][bn] = breg[i];
    }
    __syncthreads();

    unsigned long long acc2[4][2];     // [m-row][n-pair]: 4x4 fp32 accumulators
    #pragma unroll
    for (int i = 0; i < 4; i++) { acc2[i][0] = 0ULL; acc2[i][1] = 0ULL; }

    for (int it = 0; it < 16; it++) {
        const int buf = it & 1;
        const int kk  = (it + 1) << 5;
        if (it < 15) {                 // prefetch next tile
            a0 = *(const float4*)(Av + kk);
            a1 = *(const float4*)(Av + kk + 4);
            #pragma unroll
            for (int i = 0; i < 4; i++)
                breg[i] = *(const float4*)(Bp + (size_t)(kk + 8 * i) * NTQ);
        }
        #pragma unroll
        for (int k = 0; k < 32; k++) {
            float4 av = *(const float4*)&As[buf][k][ty << 2];
            ulonglong2 bp = *(const ulonglong2*)&Bs[buf][k][tx << 2];
            float a[4] = {av.x, av.y, av.z, av.w};
            #pragma unroll
            for (int i = 0; i < 4; i++) {
                unsigned long long aa = pack2(a[i], a[i]);
                ffma2(acc2[i][0], aa, bp.x);
                ffma2(acc2[i][1], aa, bp.y);
            }
        }
        if (it < 15) {                 // store into other buffer; safe pre-sync
            const int nb = buf ^ 1;
            As[nb][ak + 0][am] = a0.x * zrs[kk + ak + 0];
            As[nb][ak + 1][am] = a0.y * zrs[kk + ak + 1];
            As[nb][ak + 2][am] = a0.z * zrs[kk + ak + 2];
            As[nb][ak + 3][am] = a0.w * zrs[kk + ak + 3];
            As[nb][ak + 4][am] = a1.x * zrs[kk + ak + 4];
            As[nb][ak + 5][am] = a1.y * zrs[kk + ak + 5];
            As[nb][ak + 6][am] = a1.z * zrs[kk + ak + 6];
            As[nb][ak + 7][am] = a1.w * zrs[kk + ak + 7];
            #pragma unroll
            for (int i = 0; i < 4; i++)
                *(float4*)&Bs[nb][bk + 8 * i][bn] = breg[i];
            __syncthreads();
        }
    }

    #pragma unroll
    for (int i = 0; i < 4; i++) {
        float2 f01 = unpack2(acc2[i][0]);
        float2 f23 = unpack2(acc2[i][1]);
        float4 v = make_float4(f01.x, f01.y, f23.x, f23.y);
        *(float4*)(out + (size_t)(b * NF + m0 + (ty << 2) + i) * NTQ + n0 + (tx << 2)) = v;
    }
}

// ---------------------------------------------------------------------------
extern "C" void kernel_launch(void* const* d_in, const int* in_sizes, int n_in,
                              void* d_out, int out_size)
{
    const float* query = (const float*)d_in[0];
    const float* key   = (const float*)d_in[1];
    const float* value = (const float*)d_in[2];
    const float* W1    = (const float*)d_in[3];
    const float* W2    = (const float*)d_in[4];
    const float* vc    = (const float*)d_in[5];
    float* out = (float*)d_out;

    proj_kernel <<<dim3(128, 2), 128>>>(query, key, W1, W2);  // 2048/16 rows x {q,k}
    score_kernel<<<dim3(64, 4), 256>>>(vc);                   // TK/8 x B
    out_kernel  <<<dim3(8, 8, 4), 128>>>(value, out);         // N/64 x M/32 x B
}